// round 2
// baseline (speedup 1.0000x reference)
#include <cuda_runtime.h>

// SmileMoENorm, pair-grouped version.
//
// Insight: gamma/beta (64 KB total) were 2/3 of all L1TEX wavefronts because
// each token re-reads 16 KB of blended-affine params. Group tokens by their
// top-2 expert PAIR; then one CTA keeps (g0,g1,b0,b1) for its h-slice in
// REGISTERS and amortizes them over a 64-token chunk. x-read + out-write
// (1.03 GB) become the only significant memory traffic -> pure HBM bound.
//
// Pipeline (one CUDA graph, device-global scratch, no allocations):
//   k0_init    : sorted[] = -1, counts[] = 0
//   k1_router  : top-2 of 8 logits, w0 = sigmoid(l0-l1); count per pair
//   k2_scan    : chunk-aligned exclusive scan of counts -> cursors
//   k3_scatter : token ids into pair-sorted array (padding stays -1)
//   k4_main    : 1 CTA per 64-token chunk; 256 thr x float4 h-slice;
//                register affine params; 1 __syncthreads per token.

#define N_TOKENS    131072
#define HIDDEN      1024
#define H4          256
#define NUM_EXPERTS 8
#define EPS         1e-5f

#define C_TOK    64                               // tokens per chunk/CTA
#define N_PAIRS  64                               // e0*8+e1 ids
#define SORT_CAP (N_TOKENS + N_PAIRS * C_TOK)     // 135168
#define N_CHUNKS (SORT_CAP / C_TOK)               // 2112

__device__ int           d_sorted[SORT_CAP];
__device__ int           d_counts[N_PAIRS];
__device__ int           d_cursor[N_PAIRS];
__device__ unsigned char d_pair[N_TOKENS];
__device__ float         d_w0[N_TOKENS];

// ---------------------------------------------------------------- k0: init
__global__ void k0_init() {
    int i = blockIdx.x * blockDim.x + threadIdx.x;
    if (i < SORT_CAP) d_sorted[i] = -1;
    if (i < N_PAIRS)  d_counts[i] = 0;
}

// -------------------------------------------------------------- k1: router
__global__ void k1_router(const float4* __restrict__ logits4) {
    const int t = blockIdx.x * blockDim.x + threadIdx.x;
    const float4 la = logits4[t * 2 + 0];
    const float4 lb = logits4[t * 2 + 1];
    float l[NUM_EXPERTS] = { la.x, la.y, la.z, la.w, lb.x, lb.y, lb.z, lb.w };

    float best = l[0], second = -3.4e38f;
    int   e0 = 0,      e1 = 1;
    #pragma unroll
    for (int i = 1; i < NUM_EXPERTS; i++) {
        float v = l[i];
        if (v > best)        { second = best; e1 = e0; best = v; e0 = i; }
        else if (v > second) { second = v; e1 = i; }
    }
    // renormalized top-2 softmax weight of the best expert
    const float w0 = 1.0f / (1.0f + __expf(second - best));
    const int pair = e0 * NUM_EXPERTS + e1;
    d_pair[t] = (unsigned char)pair;
    d_w0[t]   = w0;

    // warp-aggregated histogram
    const unsigned mask = __match_any_sync(0xFFFFFFFFu, pair);
    const int lane   = threadIdx.x & 31;
    const int leader = __ffs(mask) - 1;
    if (lane == leader) atomicAdd(&d_counts[pair], __popc(mask));
}

// ---------------------------------------------------------------- k2: scan
__global__ void k2_scan() {   // 1 thread; 64 iterations, trivial
    int total = 0;
    for (int p = 0; p < N_PAIRS; p++) {
        d_cursor[p] = total;
        total += ((d_counts[p] + C_TOK - 1) / C_TOK) * C_TOK;
    }
}

// ------------------------------------------------------------- k3: scatter
__global__ void k3_scatter() {
    const int t = blockIdx.x * blockDim.x + threadIdx.x;
    const int pair = d_pair[t];
    const unsigned mask = __match_any_sync(0xFFFFFFFFu, pair);
    const int lane   = threadIdx.x & 31;
    const int leader = __ffs(mask) - 1;
    const int rank   = __popc(mask & ((1u << lane) - 1));
    int base = 0;
    if (lane == leader) base = atomicAdd(&d_cursor[pair], __popc(mask));
    base = __shfl_sync(mask, base, leader);
    d_sorted[base + rank] = t;
}

// ---------------------------------------------------------------- k4: main
__global__ __launch_bounds__(256, 5)
void k4_main(const float4* __restrict__ x,
             const float4* __restrict__ gamma,
             const float4* __restrict__ beta,
             float4* __restrict__ out) {
    __shared__ float2 red[2][8];
    const int tid  = threadIdx.x;
    const int lane = tid & 31;
    const int wid  = tid >> 5;
    const int base = blockIdx.x * C_TOK;

    int t = d_sorted[base];
    if (t < 0) return;                       // wholly-padding chunk (uniform)

    const int pair = d_pair[t];
    const int e0 = pair >> 3, e1 = pair & 7;
    // register-resident affine params for this thread's float4 h-slice
    const float4 g0 = gamma[e0 * H4 + tid];
    const float4 g1 = gamma[e1 * H4 + tid];
    const float4 b0 = beta [e0 * H4 + tid];
    const float4 b1 = beta [e1 * H4 + tid];

    float  w0 = d_w0[t];
    float4 xv = x[(size_t)t * H4 + tid];

    for (int i = 0; i < C_TOK; ++i) {
        // prefetch next token's row (overlaps with reduce+store of current)
        int tn = -1; float w0n = 0.0f;
        float4 xn = make_float4(0.f, 0.f, 0.f, 0.f);
        if (i + 1 < C_TOK) {
            tn = d_sorted[base + i + 1];
            if (tn >= 0) { w0n = d_w0[tn]; xn = x[(size_t)tn * H4 + tid]; }
        }

        // block reduction: warp shuffle -> smem(8) -> shuffle
        float s = xv.x + xv.y + xv.z + xv.w;
        float q = xv.x * xv.x + xv.y * xv.y + xv.z * xv.z + xv.w * xv.w;
        #pragma unroll
        for (int o = 16; o > 0; o >>= 1) {
            s += __shfl_xor_sync(0xFFFFFFFFu, s, o);
            q += __shfl_xor_sync(0xFFFFFFFFu, q, o);
        }
        const int buf = i & 1;
        if (lane == 0) red[buf][wid] = make_float2(s, q);
        __syncthreads();
        float2 v8 = red[buf][lane & 7];
        #pragma unroll
        for (int o = 4; o > 0; o >>= 1) {
            v8.x += __shfl_xor_sync(0xFFFFFFFFu, v8.x, o);
            v8.y += __shfl_xor_sync(0xFFFFFFFFu, v8.y, o);
        }
        const float mean = v8.x * (1.0f / HIDDEN);
        const float rstd = rsqrtf(v8.y * (1.0f / HIDDEN) - mean * mean + EPS);
        const float w1   = 1.0f - w0;

        float4 o4;
        o4.x = (xv.x - mean) * rstd * (w0 * g0.x + w1 * g1.x) + (w0 * b0.x + w1 * b1.x);
        o4.y = (xv.y - mean) * rstd * (w0 * g0.y + w1 * g1.y) + (w0 * b0.y + w1 * b1.y);
        o4.z = (xv.z - mean) * rstd * (w0 * g0.z + w1 * g1.z) + (w0 * b0.z + w1 * b1.z);
        o4.w = (xv.w - mean) * rstd * (w0 * g0.w + w1 * g1.w) + (w0 * b0.w + w1 * b1.w);
        out[(size_t)t * H4 + tid] = o4;

        if (tn < 0) return;                  // uniform: padding tail reached
        t = tn; xv = xn; w0 = w0n;
    }
}

// ------------------------------------------------------------------ launch
extern "C" void kernel_launch(void* const* d_in, const int* in_sizes, int n_in,
                              void* d_out, int out_size) {
    const float4* x       = (const float4*)d_in[0];  // hidden_states [N, H]
    const float4* logits4 = (const float4*)d_in[1];  // router_logits [N, 8]
    const float4* gamma   = (const float4*)d_in[2];  // [E, H]
    const float4* beta    = (const float4*)d_in[3];  // [E, H]
    float4* out           = (float4*)d_out;

    k0_init   <<<(SORT_CAP + 255) / 256, 256>>>();
    k1_router <<<N_TOKENS / 256, 256>>>(logits4);
    k2_scan   <<<1, 1>>>();
    k3_scatter<<<N_TOKENS / 256, 256>>>();
    k4_main   <<<N_CHUNKS, 256>>>(x, gamma, beta, out);
}